// round 12
// baseline (speedup 1.0000x reference)
#include <cuda_runtime.h>
#include <cuda_fp16.h>
#include <cstdint>
#include <cstddef>

#define B_ 2048
#define T_ 200
#define D_ 4
#define H_ 256
#define G_ 1024
#define CL 8
#define THREADS 512
#define CH 16384
#define TILE 65536

// smem layout (bytes)
#define SW_OFF  0          // weights: W0 64KB (phase A) / W1 128KB (phase B)
#define HA0_OFF 65536      // phase A: h1 buffer 0 (64KB)
#define HB_OFF  131072     // phase A: h1 buffer 1 / phase B: h2 buffer (64KB)
#define S0_OFF  196608     // phase B x slot 0 (16KB)
#define S1_OFF  212992     // phase B x slot 1 (16KB)
#define SXW_OFF 229376     // Wx fp16 (1KB)
#define SXR_OFF 230400     // x rows fp16 (1KB)
#define SMB_OFF 231424     // 3 mbarriers
#define SMEM_TOTAL 231488

// ---------------- device globals ----------------
__device__ __align__(128) __half g_W0[G_ * H_];        // pre-swizzled, 8 ranks * 64KB
__device__ __align__(128) __half g_Wx0h[G_ * D_];
__device__ __align__(128) float  g_b0[G_];
__device__ __align__(128) __half g_W1[G_ * 2 * H_];    // 8 ranks * 128KB
__device__ __align__(128) float  g_b1[G_];
__device__ __align__(128) __half g_h1seq[(size_t)T_ * B_ * H_];  // [t*16+ms] 64KB tiles
__device__ __align__(128) float  g_h2f[B_ * H_];

// swizzled image offset for (row r, col k) in [128 x K] tile, 64-col chunks
__device__ __forceinline__ size_t swoff(int r, int k) {
    int kc = k >> 6, cc = k & 63, g = cc >> 3, e = cc & 7;
    return (size_t)kc * CH + r * 128 + ((g ^ (r & 7)) << 4) + e * 2;
}
// quad-in-thread column map
__device__ __forceinline__ int col2row(int n) {
    int c = n & 31;
    int j = (n >> 5) * 8 + ((c >> 4) << 2) + ((c >> 1) & 3);
    int blk = (c >> 3) & 1, e = c & 1;
    int g = blk ? (e ? 3 : 2) : (e ? 1 : 0);
    return g * H_ + j;
}
__global__ void k_pack0(const float* __restrict__ Wi, const float* __restrict__ Wh,
                        const float* __restrict__ bi, const float* __restrict__ bh) {
    int s = gridDim.x * blockDim.x;
    for (int i = blockIdx.x * blockDim.x + threadIdx.x; i < G_ * H_; i += s) {
        int n = i >> 8, k = i & 255;
        int orow = col2row(n);
        int rank = n >> 7, r = n & 127;
        *(__half*)((char*)g_W0 + (size_t)rank * TILE + swoff(r, k)) = __float2half(Wh[orow * H_ + k]);
        if (k < D_) g_Wx0h[n * D_ + k] = __float2half(Wi[orow * D_ + k]);
        if (k == 0) g_b0[n] = bi[orow] + bh[orow];
    }
}
__global__ void k_pack1(const float* __restrict__ Wi, const float* __restrict__ Wh,
                        const float* __restrict__ bi, const float* __restrict__ bh) {
    int s = gridDim.x * blockDim.x;
    for (int i = blockIdx.x * blockDim.x + threadIdx.x; i < G_ * 512; i += s) {
        int n = i >> 9, k = i & 511;
        int orow = col2row(n);
        int rank = n >> 7, r = n & 127;
        float v = (k < H_) ? Wi[orow * H_ + k] : Wh[orow * H_ + (k - H_)];
        *(__half*)((char*)g_W1 + (size_t)rank * 131072 + swoff(r, k)) = __float2half(v);
        if (k == 0) g_b1[n] = bi[orow] + bh[orow];
    }
}

// ---------------- helpers ----------------
__device__ __forceinline__ uint32_t smem_u32(const void* p) {
    uint32_t a;
    asm("{ .reg .u64 t; cvta.to.shared.u64 t, %1; cvt.u32.u64 %0, t; }" : "=r"(a) : "l"(p));
    return a;
}
__device__ __forceinline__ void clsync() {
    asm volatile("barrier.cluster.arrive.aligned;\n" ::: "memory");
    asm volatile("barrier.cluster.wait.aligned;\n" ::: "memory");
}
__device__ __forceinline__ float tanha_(float x) {
    float r; asm("tanh.approx.f32 %0, %1;" : "=f"(r) : "f"(x));
    return r;
}
__device__ __forceinline__ float siga_(float x) { return __fmaf_rn(tanha_(0.5f * x), 0.5f, 0.5f); }
__device__ __forceinline__ void mbar_init(uint32_t m, uint32_t c) {
    asm volatile("mbarrier.init.shared.b64 [%0], %1;" :: "r"(m), "r"(c) : "memory");
}
__device__ __forceinline__ void bulk_in(uint32_t sdst, const void* g, uint32_t bytes, uint32_t mb) {
    asm volatile("mbarrier.arrive.expect_tx.shared.b64 _, [%0], %1;" :: "r"(mb), "r"(bytes) : "memory");
    asm volatile("cp.async.bulk.shared::cluster.global.mbarrier::complete_tx::bytes [%0], [%1], %2, [%3];"
                 :: "r"(sdst), "l"(g), "r"(bytes), "r"(mb) : "memory");
}
__device__ __forceinline__ void mbar_wait(uint32_t m, uint32_t par) {
    uint32_t done;
    asm volatile("{.reg .pred p; mbarrier.try_wait.parity.acquire.cta.shared::cta.b64 p, [%1], %2; selp.b32 %0,1,0,p;}"
                 : "=r"(done) : "r"(m), "r"(par) : "memory");
    if (!done) {
        asm volatile(
            "{.reg .pred P1;\nWL_%=:\n"
            "mbarrier.try_wait.parity.acquire.cta.shared::cta.b64 P1, [%0], %1, 0x989680;\n"
            "@P1 bra.uni WD_%=;\nbra.uni WL_%=;\nWD_%=:\n}"
            :: "r"(m), "r"(par) : "memory");
    }
}
__device__ __forceinline__ void load4h(const __half* p, float f[4]) {
    uint2 u = *(const uint2*)p;
    __half2 h0 = *reinterpret_cast<__half2*>(&u.x);
    __half2 h1 = *reinterpret_cast<__half2*>(&u.y);
    float2 a = __half22float2(h0), b = __half22float2(h1);
    f[0] = a.x; f[1] = a.y; f[2] = b.x; f[3] = b.y;
}

// ---------------- GEMM on one resident chunk ----------------
__device__ __forceinline__ void gemm_chunk(
    const char* smem, int aoff, int boff, float (&acc)[2][4][4],
    int wm, int wn, int a_rowoff, int a_half, int b_rowoff, int b_half)
{
    const __half* sA = (const __half*)(smem + aoff);
    const __half* sB = (const __half*)(smem + boff);
#pragma unroll
    for (int k16 = 0; k16 < 4; k16++) {
        uint32_t afr[2][4];
#pragma unroll
        for (int mi = 0; mi < 2; mi++) {
            int r = wm * 32 + mi * 16 + a_rowoff;
            int cch = (k16 * 2 + a_half) ^ (r & 7);
            uint32_t ad = (uint32_t)__cvta_generic_to_shared(sA + r * 64 + cch * 8);
            asm volatile("ldmatrix.sync.aligned.m8n8.x4.shared.b16 {%0,%1,%2,%3}, [%4];"
                         : "=r"(afr[mi][0]), "=r"(afr[mi][1]), "=r"(afr[mi][2]), "=r"(afr[mi][3])
                         : "r"(ad));
        }
        uint32_t bfr[2][4];
#pragma unroll
        for (int np = 0; np < 2; np++) {
            int r = wn * 32 + np * 16 + b_rowoff;
            int cch = (k16 * 2 + b_half) ^ (r & 7);
            uint32_t ad = (uint32_t)__cvta_generic_to_shared(sB + r * 64 + cch * 8);
            asm volatile("ldmatrix.sync.aligned.m8n8.x4.shared.b16 {%0,%1,%2,%3}, [%4];"
                         : "=r"(bfr[np][0]), "=r"(bfr[np][1]), "=r"(bfr[np][2]), "=r"(bfr[np][3])
                         : "r"(ad));
        }
#pragma unroll
        for (int mi = 0; mi < 2; mi++)
#pragma unroll
            for (int nj = 0; nj < 4; nj++) {
                uint32_t b0 = bfr[nj >> 1][(nj & 1) * 2 + 0];
                uint32_t b1 = bfr[nj >> 1][(nj & 1) * 2 + 1];
                asm volatile(
                    "mma.sync.aligned.m16n8k16.row.col.f32.f16.f16.f32 "
                    "{%0,%1,%2,%3}, {%4,%5,%6,%7}, {%8,%9}, {%0,%1,%2,%3};"
                    : "+f"(acc[mi][nj][0]), "+f"(acc[mi][nj][1]),
                      "+f"(acc[mi][nj][2]), "+f"(acc[mi][nj][3])
                    : "r"(afr[mi][0]), "r"(afr[mi][1]), "r"(afr[mi][2]), "r"(afr[mi][3]),
                      "r"(b0), "r"(b1));
            }
    }
}

// ---------------- pointwise: gates -> c,h; write own col-slice into image ----------------
template<bool XPROJ, bool FIN>
__device__ __forceinline__ void pointwise_img(
    float (&acc)[2][4][4], float* c, const float* biasr,
    char* smem, int img_off, float* fdst, int lane, int wm, int wn, int rank)
{
    const int q = lane & 3;
    const __half* sxr = (const __half*)(smem + SXR_OFF);
    const __half* sxw = (const __half*)(smem + SXW_OFF);
#pragma unroll
    for (int mi = 0; mi < 2; mi++) {
        int r0 = wm * 32 + mi * 16 + (lane >> 2);
        float a[4][4], xlo[4], xhi[4];
        if (XPROJ) { load4h(sxr + r0 * 4, xlo); load4h(sxr + (r0 + 8) * 4, xhi); }
#pragma unroll
        for (int nj = 0; nj < 4; nj++) {
            a[nj][0] = acc[mi][nj][0] + biasr[nj * 2 + 0];
            a[nj][1] = acc[mi][nj][1] + biasr[nj * 2 + 1];
            a[nj][2] = acc[mi][nj][2] + biasr[nj * 2 + 0];
            a[nj][3] = acc[mi][nj][3] + biasr[nj * 2 + 1];
            if (XPROJ) {
                int cl = wn * 32 + nj * 8 + q * 2;
                float w0[4], w1[4];
                load4h(sxw + cl * 4, w0); load4h(sxw + cl * 4 + 4, w1);
                a[nj][0] += xlo[0]*w0[0] + xlo[1]*w0[1] + xlo[2]*w0[2] + xlo[3]*w0[3];
                a[nj][1] += xlo[0]*w1[0] + xlo[1]*w1[1] + xlo[2]*w1[2] + xlo[3]*w1[3];
                a[nj][2] += xhi[0]*w0[0] + xhi[1]*w0[1] + xhi[2]*w0[2] + xhi[3]*w0[3];
                a[nj][3] += xhi[0]*w1[0] + xhi[1]*w1[1] + xhi[2]*w1[2] + xhi[3]*w1[3];
            }
        }
#pragma unroll
        for (int us = 0; us < 2; us++)
#pragma unroll
            for (int ru = 0; ru < 2; ru++) {
                float gi = a[us*2][ru*2], gf = a[us*2][ru*2+1];
                float gg = a[us*2+1][ru*2], go = a[us*2+1][ru*2+1];
                int ci = mi * 4 + us * 2 + ru;
                float iv = siga_(gi), fv = siga_(gf), gv = tanha_(gg), ov = siga_(go);
                float cn = fv * c[ci] + iv * gv;
                c[ci] = cn;
                float h = ov * tanha_(cn);
                int row = r0 + ru * 8;
                int k = rank * 32 + wn * 8 + q + us * 4;
                if (FIN) {
                    fdst[(size_t)row * H_ + k] = h;
                } else {
                    size_t off = (size_t)(k >> 6) * CH + row * 128
                               + ((((k & 63) >> 3) ^ (row & 7)) << 4) + (k & 7) * 2;
                    *(__half*)(smem + img_off + off) = __float2half(h);
                }
            }
    }
}

// each thread: 1 granule of own 32-col slice -> 7 peers (+ optional global)
__device__ __forceinline__ void scatter7(char* smem, int img_off, char* gdst, int tid, int rank) {
    int row = tid >> 2, gg2 = tid & 3;
    int kcc = rank >> 1;
    int g2 = ((rank & 1) << 2) | gg2;
    uint32_t off = (uint32_t)kcc * CH + row * 128 + (uint32_t)((g2 ^ (row & 7)) << 4);
    uint4 v = *(uint4*)(smem + img_off + off);
    if (gdst) *(uint4*)(gdst + off) = v;
    uint32_t la = smem_u32(smem + img_off) + off;
#pragma unroll
    for (int p = 0; p < CL; p++) {
        if (p == rank) continue;
        uint32_t ra;
        asm volatile("mapa.shared::cluster.u32 %0, %1, %2;" : "=r"(ra) : "r"(la), "r"(p));
        asm volatile("st.shared::cluster.v4.b32 [%0], {%1,%2,%3,%4};"
                     :: "r"(ra), "r"(v.x), "r"(v.y), "r"(v.z), "r"(v.w) : "memory");
    }
}

// ---------------- persistent kernel ----------------
__global__ void __cluster_dims__(CL, 1, 1) __launch_bounds__(THREADS, 1)
k_lstm(const float* __restrict__ x)
{
    extern __shared__ __align__(1024) char smem[];
    uint32_t sb = smem_u32(smem);
    const int tid = threadIdx.x, lane = tid & 31, warp = tid >> 5;
    const int wm = warp & 3, wn = warp >> 2;
    const int rank = blockIdx.x, ms = blockIdx.y;
    const int mbase = ms * 128, nbase = rank * 128;
    const int q = lane & 3;
    const int lg = lane >> 3, lr = lane & 7;
    const int a_rowoff = lr + ((lg & 1) << 3), a_half = lg >> 1;
    const int b_rowoff = lr + ((lg >> 1) << 3), b_half = lg & 1;

    const uint32_t mbS0 = sb + SMB_OFF, mbS1 = sb + SMB_OFF + 8, mbW = sb + SMB_OFF + 16;
    if (tid == 0) { mbar_init(mbS0, 1); mbar_init(mbS1, 1); mbar_init(mbW, 1); }
    __syncthreads();

    float biasr[8], c[8];
    int uc0 = 0, uc1 = 0;
    auto h1t = [&](int t) -> char* { return (char*)g_h1seq + ((size_t)t * 16 + ms) * TILE; };

    // ---- phase A setup: W0 resident, HA0 zeroed ----
    if (tid == 0) bulk_in(sb + SW_OFF, (char*)g_W0 + (size_t)rank * TILE, TILE, mbW);
    if (tid < 128)
        *(uint2*)((__half*)(smem + SXW_OFF) + tid * 4) = *(const uint2*)&g_Wx0h[(nbase + tid) * 4];
#pragma unroll
    for (int nj = 0; nj < 4; nj++) {
        biasr[nj * 2 + 0] = g_b0[nbase + wn * 32 + nj * 8 + q * 2 + 0];
        biasr[nj * 2 + 1] = g_b0[nbase + wn * 32 + nj * 8 + q * 2 + 1];
    }
#pragma unroll
    for (int i = 0; i < 8; i++) c[i] = 0.f;
#pragma unroll
    for (int i = 0; i < 8; i++)
        *(uint4*)(smem + HA0_OFF + tid * 16 + i * 8192) = make_uint4(0, 0, 0, 0);
    mbar_wait(mbW, 0);
    __syncthreads();
    clsync();

    // ---- phase A: layer 0, h1 double-buffered in smem, zero dependent TMA ----
#pragma unroll 1
    for (int t = 0; t < T_; t++) {
        int bufc = (t & 1) ? HB_OFF : HA0_OFF;
        int bufn = (t & 1) ? HA0_OFF : HB_OFF;
        if (tid < 128) {
            float4 v = *(const float4*)(x + ((size_t)(mbase + tid) * T_ + t) * D_);
            __half2 p0 = __floats2half2_rn(v.x, v.y), p1 = __floats2half2_rn(v.z, v.w);
            uint2 u; u.x = *reinterpret_cast<uint32_t*>(&p0); u.y = *reinterpret_cast<uint32_t*>(&p1);
            *(uint2*)((__half*)(smem + SXR_OFF) + tid * 4) = u;
        }
        float acc[2][4][4];
#pragma unroll
        for (int mi = 0; mi < 2; mi++)
#pragma unroll
            for (int nj = 0; nj < 4; nj++)
#pragma unroll
                for (int e = 0; e < 4; e++) acc[mi][nj][e] = 0.f;
#pragma unroll
        for (int kc = 0; kc < 4; kc++)
            gemm_chunk(smem, bufc + kc * CH, SW_OFF + kc * CH, acc,
                       wm, wn, a_rowoff, a_half, b_rowoff, b_half);
        __syncthreads();
        pointwise_img<true, false>(acc, c, biasr, smem, bufn, nullptr, lane, wm, wn, rank);
        __syncthreads();
        scatter7(smem, bufn, h1t(t), tid, rank);
        clsync();
    }

    // ---- phase boundary: W1 resident, h2 buffer zeroed, x(0) prefetch ----
    asm volatile("fence.proxy.async;" ::: "memory");
    clsync();
    if (tid == 0) {
        bulk_in(sb + SW_OFF, (char*)g_W1 + (size_t)rank * 131072, 131072, mbW);
        bulk_in(sb + S0_OFF, h1t(0) + 0 * CH, CH, mbS0);
        bulk_in(sb + S1_OFF, h1t(0) + 1 * CH, CH, mbS1);
    }
#pragma unroll
    for (int nj = 0; nj < 4; nj++) {
        biasr[nj * 2 + 0] = g_b1[nbase + wn * 32 + nj * 8 + q * 2 + 0];
        biasr[nj * 2 + 1] = g_b1[nbase + wn * 32 + nj * 8 + q * 2 + 1];
    }
#pragma unroll
    for (int i = 0; i < 8; i++) c[i] = 0.f;
#pragma unroll
    for (int i = 0; i < 8; i++)
        *(uint4*)(smem + HB_OFF + tid * 16 + i * 8192) = make_uint4(0, 0, 0, 0);
    mbar_wait(mbW, 1);
    __syncthreads();
    clsync();

    // ---- phase B: layer 1, h2 resident (single buffer), x streamed+prefetched ----
#pragma unroll 1
    for (int t = 0; t < T_; t++) {
        bool fin = (t == T_ - 1);
        float acc[2][4][4];
#pragma unroll
        for (int mi = 0; mi < 2; mi++)
#pragma unroll
            for (int nj = 0; nj < 4; nj++)
#pragma unroll
                for (int e = 0; e < 4; e++) acc[mi][nj][e] = 0.f;
        mbar_wait(mbS0, uc0 & 1); uc0++;
        gemm_chunk(smem, S0_OFF, SW_OFF + 0 * CH, acc, wm, wn, a_rowoff, a_half, b_rowoff, b_half);
        __syncthreads();
        if (tid == 0) bulk_in(sb + S0_OFF, h1t(t) + 2 * CH, CH, mbS0);
        mbar_wait(mbS1, uc1 & 1); uc1++;
        gemm_chunk(smem, S1_OFF, SW_OFF + 1 * CH, acc, wm, wn, a_rowoff, a_half, b_rowoff, b_half);
        __syncthreads();
        if (tid == 0) bulk_in(sb + S1_OFF, h1t(t) + 3 * CH, CH, mbS1);
        mbar_wait(mbS0, uc0 & 1); uc0++;
        gemm_chunk(smem, S0_OFF, SW_OFF + 2 * CH, acc, wm, wn, a_rowoff, a_half, b_rowoff, b_half);
        mbar_wait(mbS1, uc1 & 1); uc1++;
        gemm_chunk(smem, S1_OFF, SW_OFF + 3 * CH, acc, wm, wn, a_rowoff, a_half, b_rowoff, b_half);
#pragma unroll
        for (int kc = 0; kc < 4; kc++)
            gemm_chunk(smem, HB_OFF + kc * CH, SW_OFF + (4 + kc) * CH, acc,
                       wm, wn, a_rowoff, a_half, b_rowoff, b_half);
        clsync();   // all HB reads + slot reads complete cluster-wide
        if (tid == 0 && t + 1 < T_) {
            bulk_in(sb + S0_OFF, h1t(t + 1) + 0 * CH, CH, mbS0);
            bulk_in(sb + S1_OFF, h1t(t + 1) + 1 * CH, CH, mbS1);
        }
        if (fin) {
            pointwise_img<false, true>(acc, c, biasr, smem, 0,
                                       g_h2f + (size_t)mbase * H_, lane, wm, wn, rank);
        } else {
            pointwise_img<false, false>(acc, c, biasr, smem, HB_OFF, nullptr, lane, wm, wn, rank);
            __syncthreads();
            scatter7(smem, HB_OFF, nullptr, tid, rank);
        }
        clsync();   // scatters visible before next step's reads
    }
}

// ---------------- final FC ----------------
__global__ void k_fc(const float* __restrict__ Wfc, const float* __restrict__ bfc,
                     float* __restrict__ out) {
    int b = blockIdx.x;
    int o = threadIdx.y;
    int lane = threadIdx.x;
    const float* hr = g_h2f + (size_t)b * H_;
    const float* wr = Wfc + (size_t)o * H_;
    float s = 0.f;
    for (int j = lane; j < H_; j += 32) s += hr[j] * wr[j];
#pragma unroll
    for (int off = 16; off; off >>= 1) s += __shfl_xor_sync(0xffffffffu, s, off);
    if (lane == 0) out[b * 6 + o] = s + bfc[o];
}

// ---------------- host ----------------
extern "C" void kernel_launch(void* const* d_in, const int* in_sizes, int n_in,
                              void* d_out, int out_size) {
    const float* x     = (const float*)d_in[0];
    const float* W_ih0 = (const float*)d_in[1];
    const float* W_hh0 = (const float*)d_in[2];
    const float* b_ih0 = (const float*)d_in[3];
    const float* b_hh0 = (const float*)d_in[4];
    const float* W_ih1 = (const float*)d_in[5];
    const float* W_hh1 = (const float*)d_in[6];
    const float* b_ih1 = (const float*)d_in[7];
    const float* b_hh1 = (const float*)d_in[8];
    const float* W_fc  = (const float*)d_in[9];
    const float* b_fc  = (const float*)d_in[10];

    cudaFuncSetAttribute(k_lstm, cudaFuncAttributeMaxDynamicSharedMemorySize, SMEM_TOTAL);

    k_pack0<<<512, 256>>>(W_ih0, W_hh0, b_ih0, b_hh0);
    k_pack1<<<1024, 256>>>(W_ih1, W_hh1, b_ih1, b_hh1);

    k_lstm<<<dim3(CL, 16), THREADS, SMEM_TOTAL>>>(x);

    k_fc<<<B_, dim3(32, 6)>>>(W_fc, b_fc, (float*)d_out);
}